// round 6
// baseline (speedup 1.0000x reference)
#include <cuda_runtime.h>
#include <cstdint>

#define NHEADS 12
#define HD 64
#define NB 16
#define SEQ 577
#define DIM 768
#define MROWS (NB * SEQ)        // 9232
#define NQKV (3 * DIM)          // 2304
#define NBH (NB * NHEADS)       // 192
#define ATT_SCALE 0.125f
#define EPSF 1e-6f
#define AST 36                  // A smem stride: banks g*36+t -> 4g+t, conflict-free
#define BST 72                  // B smem stride: banks t*72+g -> 8t+g, conflict-free
#define KST 68                  // attn smem stride

// Scratch (no allocations allowed)
__device__ float g_qkv[(size_t)3 * NBH * SEQ * HD];   // [3,B,H,N,64]
__device__ float g_attn[(size_t)MROWS * DIM];         // [B*N, 768]
__device__ float g_vsum[(size_t)NBH * HD];            // per (b,h): sum_keys V

__device__ __forceinline__ uint32_t f2tf32(float x) {
    uint32_t r;
    asm("cvt.rna.tf32.f32 %0, %1;" : "=r"(r) : "f"(x));
    return r;
}
__device__ __forceinline__ void mma1688(float d[4], const uint32_t a[4], const uint32_t b[2]) {
    asm volatile(
        "mma.sync.aligned.m16n8k8.row.col.f32.tf32.tf32.f32 "
        "{%0,%1,%2,%3}, {%4,%5,%6,%7}, {%8,%9}, {%0,%1,%2,%3};"
        : "+f"(d[0]), "+f"(d[1]), "+f"(d[2]), "+f"(d[3])
        : "r"(a[0]), "r"(a[1]), "r"(a[2]), "r"(a[3]), "r"(b[0]), "r"(b[1]));
}
__device__ __forceinline__ float4 round4(float4 v) {
    float4 w;
    w.x = __uint_as_float(f2tf32(v.x));
    w.y = __uint_as_float(f2tf32(v.y));
    w.z = __uint_as_float(f2tf32(v.z));
    w.w = __uint_as_float(f2tf32(v.w));
    return w;
}

// ---------------------------------------------------------------------------
// Double-buffered tf32 mma GEMM.
// C[m0:+128, n0:+64] = A[.,768] @ W[768, ldB][:, n0:+64]  (+bias)
// W consumed in ORIGINAL [k][n] layout (no pre-transpose needed for row.col).
// 8 warps = 4M x 2N, warp tile 32x32, K-tile 32, 1 sync per K-tile.
// mode 0: scatter into g_qkv; mode 1: row-major out.
// ---------------------------------------------------------------------------
__global__ __launch_bounds__(256, 2) void gemm_mma(const float* __restrict__ A,
                                                   const float* __restrict__ W,
                                                   const float* __restrict__ bias,
                                                   float* __restrict__ outp,
                                                   int Mtotal, int ldB, int mode) {
    extern __shared__ float smg[];
    float* As[2] = {smg, smg + 128 * AST};                       // 128 x 32 each
    float* Bs[2] = {smg + 2 * 128 * AST, smg + 2 * 128 * AST + 32 * BST};  // 32 x 64

    const int tid = threadIdx.x;
    const int lane = tid & 31, wid = tid >> 5;
    const int warpM = wid >> 1, warpN = wid & 1;
    const int g = lane >> 2, t = lane & 3;
    const int m0 = blockIdx.y * 128, n0 = blockIdx.x * 64;

    // prefetch registers
    float4 pa[4], pb[2];
    const int ar = tid >> 1, ac4 = (tid & 1) << 2;   // A: 2 thr/row, 2 float4-slots... (see loads)
    (void)ar; (void)ac4;

    // A: 1024 float4 -> 4/thread: r = idx>>3, c4 = idx&7
    // B: 32 x 64 = 512 float4 -> 2/thread: r = idx>>4, c4 = idx&15
#define LDG_TILE(kt)                                                            \
    {                                                                           \
        const int k0 = (kt) * 32;                                               \
        _Pragma("unroll")                                                       \
        for (int u = 0; u < 4; u++) {                                           \
            int idx = tid + u * 256;                                            \
            int r = idx >> 3, c4 = idx & 7;                                     \
            pa[u] = make_float4(0.f, 0.f, 0.f, 0.f);                            \
            if (m0 + r < Mtotal)                                                \
                pa[u] = *(const float4*)(A + (size_t)(m0 + r) * DIM + k0 + c4 * 4); \
        }                                                                       \
        _Pragma("unroll")                                                       \
        for (int u = 0; u < 2; u++) {                                           \
            int idx = tid + u * 256;                                            \
            int r = idx >> 4, c4 = idx & 15;                                    \
            pb[u] = *(const float4*)(W + (size_t)(k0 + r) * ldB + n0 + c4 * 4); \
        }                                                                       \
    }

#define STS_TILE(buf)                                                           \
    {                                                                           \
        _Pragma("unroll")                                                       \
        for (int u = 0; u < 4; u++) {                                           \
            int idx = tid + u * 256;                                            \
            int r = idx >> 3, c4 = idx & 7;                                     \
            *(float4*)(As[buf] + r * AST + c4 * 4) = round4(pa[u]);             \
        }                                                                       \
        _Pragma("unroll")                                                       \
        for (int u = 0; u < 2; u++) {                                           \
            int idx = tid + u * 256;                                            \
            int r = idx >> 4, c4 = idx & 15;                                    \
            *(float4*)(Bs[buf] + r * BST + c4 * 4) = round4(pb[u]);             \
        }                                                                       \
    }

    float d[2][4][4];
#pragma unroll
    for (int i = 0; i < 2; i++)
#pragma unroll
        for (int j = 0; j < 4; j++)
#pragma unroll
            for (int c = 0; c < 4; c++) d[i][j][c] = 0.f;

    LDG_TILE(0);
    STS_TILE(0);
    __syncthreads();

    for (int kt = 0; kt < 24; kt++) {
        const int cur = kt & 1;
        if (kt < 23) LDG_TILE(kt + 1);

        const float* Ab = As[cur];
        const float* Bb = Bs[cur];
#pragma unroll
        for (int ks = 0; ks < 4; ks++) {
            const int kb = ks * 8;
            uint32_t af[2][4], bf[4][2];
#pragma unroll
            for (int mf = 0; mf < 2; mf++) {
                int r0 = warpM * 32 + mf * 16 + g;
                af[mf][0] = __float_as_uint(Ab[r0 * AST + kb + t]);
                af[mf][1] = __float_as_uint(Ab[(r0 + 8) * AST + kb + t]);
                af[mf][2] = __float_as_uint(Ab[r0 * AST + kb + t + 4]);
                af[mf][3] = __float_as_uint(Ab[(r0 + 8) * AST + kb + t + 4]);
            }
#pragma unroll
            for (int nf = 0; nf < 4; nf++) {
                int c0 = warpN * 32 + nf * 8 + g;
                bf[nf][0] = __float_as_uint(Bb[(kb + t) * BST + c0]);
                bf[nf][1] = __float_as_uint(Bb[(kb + t + 4) * BST + c0]);
            }
#pragma unroll
            for (int mf = 0; mf < 2; mf++)
#pragma unroll
                for (int nf = 0; nf < 4; nf++) mma1688(d[mf][nf], af[mf], bf[nf]);
        }
        if (kt < 23) STS_TILE(1 - cur);
        __syncthreads();
    }

#pragma unroll
    for (int mf = 0; mf < 2; mf++) {
#pragma unroll
        for (int half = 0; half < 2; half++) {
            int row = m0 + warpM * 32 + mf * 16 + g + half * 8;
            if (row >= Mtotal) continue;
            int b_ = row / SEQ, n = row - (row / SEQ) * SEQ;
#pragma unroll
            for (int nf = 0; nf < 4; nf++) {
                int col = n0 + warpN * 32 + nf * 8 + 2 * t;
                float2 w;
                w.x = d[mf][nf][half * 2 + 0] + bias[col + 0];
                w.y = d[mf][nf][half * 2 + 1] + bias[col + 1];
                if (mode == 0) {
                    int s = col / DIM;
                    int rem = col - s * DIM;
                    int h = rem >> 6, dd = rem & 63;
                    *(float2*)(g_qkv +
                        (((size_t)s * NBH + b_ * NHEADS + h) * SEQ + n) * HD + dd) = w;
                } else {
                    *(float2*)(outp + (size_t)row * DIM + col) = w;
                }
            }
        }
    }
#undef LDG_TILE
#undef STS_TILE
}

// ---------------------------------------------------------------------------
// Per-(b,h) column sums of V, 256 threads: 4 row-groups x 64 cols + reduce.
// ---------------------------------------------------------------------------
__global__ __launch_bounds__(256) void vsum_kernel() {
    __shared__ float part[4][64];
    const int bh = blockIdx.x;
    const int c = threadIdx.x & 63, gr = threadIdx.x >> 6;
    const float* Vg = g_qkv + (size_t)(2 * NBH + bh) * SEQ * HD;
    float s = 0.f;
    for (int k = gr; k < SEQ; k += 4) s += Vg[(size_t)k * HD + c];
    part[gr][c] = s;
    __syncthreads();
    if (gr == 0)
        g_vsum[bh * HD + c] = part[0][c] + part[1][c] + part[2][c] + part[3][c];
}

// ---------------------------------------------------------------------------
// Tensor-core attention (unchanged from R5, validated).
// ---------------------------------------------------------------------------
__global__ __launch_bounds__(256, 2) void attn_mma(const float* __restrict__ policy) {
    extern __shared__ float sm[];
    float* Ks = sm;
    float* Vs = sm + 64 * KST;
    float* Ps = sm + 128 * KST;
    float* pol = sm + 256 * KST;

    const int bh = blockIdx.y;
    const int b_ = bh / NHEADS, h = bh % NHEADS;
    const int q0 = blockIdx.x * 128;
    const float* Qg = g_qkv + (size_t)bh * SEQ * HD;
    const float* Kg = g_qkv + (size_t)(NBH + bh) * SEQ * HD;
    const float* Vg = g_qkv + (size_t)(2 * NBH + bh) * SEQ * HD;

    const int tid = threadIdx.x;
    const int lane = tid & 31, w = tid >> 5;
    const int g = lane >> 2, t = lane & 3;
    const int r0 = q0 + w * 16 + g;

    uint32_t aq[8][4];
#pragma unroll
    for (int ks = 0; ks < 8; ks++) {
        int c = ks * 8 + t;
        aq[ks][0] = (r0 < SEQ)     ? f2tf32(Qg[(size_t)r0 * HD + c])           : 0u;
        aq[ks][1] = (r0 + 8 < SEQ) ? f2tf32(Qg[(size_t)(r0 + 8) * HD + c])     : 0u;
        aq[ks][2] = (r0 < SEQ)     ? f2tf32(Qg[(size_t)r0 * HD + c + 4])       : 0u;
        aq[ks][3] = (r0 + 8 < SEQ) ? f2tf32(Qg[(size_t)(r0 + 8) * HD + c + 4]) : 0u;
    }

    float mrow[2] = {-1e30f, -1e30f}, lrow[2] = {0.f, 0.f};
    float o[8][4];
#pragma unroll
    for (int nf = 0; nf < 8; nf++)
#pragma unroll
        for (int c = 0; c < 4; c++) o[nf][c] = 0.f;

    for (int kc = 0; kc < 10; kc++) {
        const int kb = kc * 64;
        __syncthreads();
#pragma unroll
        for (int u = 0; u < 4; u++) {
            int idx = tid + u * 256;
            int r = idx >> 4, c4 = idx & 15;
            float4 v = make_float4(0.f, 0.f, 0.f, 0.f);
            if (kb + r < SEQ) v = *(const float4*)(Kg + (size_t)(kb + r) * HD + c4 * 4);
            *(float4*)(Ks + r * KST + c4 * 4) = round4(v);
        }
#pragma unroll
        for (int u = 0; u < 4; u++) {
            int idx = tid + u * 256;
            int r = idx >> 4, c4 = idx & 15;
            float4 v = make_float4(0.f, 0.f, 0.f, 0.f);
            if (kb + r < SEQ) v = *(const float4*)(Vg + (size_t)(kb + r) * HD + c4 * 4);
            *(float4*)(Vs + r * KST + c4 * 4) = round4(v);
        }
        if (tid < 64) pol[tid] = (kb + tid < SEQ) ? policy[b_ * SEQ + kb + tid] : 0.f;
        __syncthreads();

        float s[8][4];
#pragma unroll
        for (int nf = 0; nf < 8; nf++)
#pragma unroll
            for (int c = 0; c < 4; c++) s[nf][c] = 0.f;
#pragma unroll
        for (int ks = 0; ks < 8; ks++) {
            const int kcol = ks * 8;
#pragma unroll
            for (int nf = 0; nf < 8; nf++) {
                uint32_t bf[2];
                bf[0] = __float_as_uint(Ks[(nf * 8 + g) * KST + kcol + t]);
                bf[1] = __float_as_uint(Ks[(nf * 8 + g) * KST + kcol + t + 4]);
                mma1688(s[nf], aq[ks], bf);
            }
        }

#pragma unroll
        for (int nf = 0; nf < 8; nf++)
#pragma unroll
            for (int c = 0; c < 4; c++) {
                int key = kb + nf * 8 + 2 * t + (c & 1);
                s[nf][c] = (key < SEQ) ? s[nf][c] * ATT_SCALE : -1e30f;
            }

#pragma unroll
        for (int half = 0; half < 2; half++) {
            const int qglob = r0 + 8 * half;
            float rm = -1e30f;
#pragma unroll
            for (int nf = 0; nf < 8; nf++)
                rm = fmaxf(rm, fmaxf(s[nf][half * 2], s[nf][half * 2 + 1]));
            rm = fmaxf(rm, __shfl_xor_sync(0xffffffffu, rm, 1));
            rm = fmaxf(rm, __shfl_xor_sync(0xffffffffu, rm, 2));
            float nm = fmaxf(mrow[half], rm);
            float corr = __expf(mrow[half] - nm);
            mrow[half] = nm;
            float ls = 0.f;
#pragma unroll
            for (int nf = 0; nf < 8; nf++) {
#pragma unroll
                for (int c = 0; c < 2; c++) {
                    int kl = nf * 8 + 2 * t + c;
                    int key = kb + kl;
                    bool keep = (pol[kl] > 0.5f) || (key == qglob);
                    float p = keep ? __expf(s[nf][half * 2 + c] - nm) : 0.f;
                    s[nf][half * 2 + c] = p;
                    ls += p;
                }
            }
            ls += __shfl_xor_sync(0xffffffffu, ls, 1);
            ls += __shfl_xor_sync(0xffffffffu, ls, 2);
            lrow[half] = lrow[half] * corr + ls;
#pragma unroll
            for (int nf = 0; nf < 8; nf++) {
                o[nf][half * 2] *= corr;
                o[nf][half * 2 + 1] *= corr;
            }
        }

#pragma unroll
        for (int nf = 0; nf < 8; nf++) {
#pragma unroll
            for (int half = 0; half < 2; half++) {
                float2 pv;
                pv.x = __uint_as_float(f2tf32(s[nf][half * 2]));
                pv.y = __uint_as_float(f2tf32(s[nf][half * 2 + 1]));
                *(float2*)(Ps + (w * 16 + g + 8 * half) * KST + nf * 8 + 2 * t) = pv;
            }
        }

#pragma unroll
        for (int ks = 0; ks < 8; ks++) {
            uint32_t ap[4];
            const int kcol = ks * 8;
            ap[0] = __float_as_uint(Ps[(w * 16 + g) * KST + kcol + t]);
            ap[1] = __float_as_uint(Ps[(w * 16 + g + 8) * KST + kcol + t]);
            ap[2] = __float_as_uint(Ps[(w * 16 + g) * KST + kcol + t + 4]);
            ap[3] = __float_as_uint(Ps[(w * 16 + g + 8) * KST + kcol + t + 4]);
#pragma unroll
            for (int nf = 0; nf < 8; nf++) {
                uint32_t bf[2];
                bf[0] = __float_as_uint(Vs[(kcol + t) * KST + nf * 8 + g]);
                bf[1] = __float_as_uint(Vs[(kcol + t + 4) * KST + nf * 8 + g]);
                mma1688(o[nf], ap, bf);
            }
        }
    }

    const float epsn = EPSF / (float)SEQ;
#pragma unroll
    for (int half = 0; half < 2; half++) {
        int qglob = r0 + 8 * half;
        if (qglob >= SEQ) continue;
        float inv = 1.f / (lrow[half] + EPSF);
#pragma unroll
        for (int nf = 0; nf < 8; nf++) {
            int dd = nf * 8 + 2 * t;
            float2 vs = *(const float2*)(g_vsum + bh * HD + dd);
            float2 ww;
            ww.x = (o[nf][half * 2] + epsn * vs.x) * inv;
            ww.y = (o[nf][half * 2 + 1] + epsn * vs.y) * inv;
            *(float2*)(g_attn + ((size_t)b_ * SEQ + qglob) * DIM + h * HD + dd) = ww;
        }
    }
}

// ---------------------------------------------------------------------------
extern "C" void kernel_launch(void* const* d_in, const int* in_sizes, int n_in,
                              void* d_out, int out_size) {
    const float* x      = (const float*)d_in[0];
    const float* policy = (const float*)d_in[1];
    const float* Wqkv   = (const float*)d_in[2];
    const float* bqkv   = (const float*)d_in[3];
    const float* Wproj  = (const float*)d_in[4];
    const float* bproj  = (const float*)d_in[5];
    float* out = (float*)d_out;
    (void)in_sizes; (void)n_in; (void)out_size;

    void* p_attn = nullptr;
    cudaGetSymbolAddress(&p_attn, g_attn);

    const int gsmem = (2 * 128 * AST + 2 * 32 * BST) * 4;  // 55296 B
    cudaFuncSetAttribute(gemm_mma, cudaFuncAttributeMaxDynamicSharedMemorySize, gsmem);

    // 1) QKV projection (tensor cores, direct [k][n] weights), scatter
    dim3 g1(NQKV / 64, (MROWS + 127) / 128);
    gemm_mma<<<g1, 256, gsmem>>>(x, Wqkv, bqkv, nullptr, MROWS, NQKV, 0);

    // 1b) per-(b,h) V column sums
    vsum_kernel<<<NBH, 256>>>();

    // 2) tensor-core policy-masked flash attention
    const int asmem = (256 * KST + 64) * 4;
    cudaFuncSetAttribute(attn_mma, cudaFuncAttributeMaxDynamicSharedMemorySize, asmem);
    dim3 g2((SEQ + 127) / 128, NBH);
    attn_mma<<<g2, 256, asmem>>>(policy);

    // 3) output projection (tensor cores)
    dim3 g3(DIM / 64, (MROWS + 127) / 128);
    gemm_mma<<<g3, 256, gsmem>>>((const float*)p_attn, Wproj, bproj, out, MROWS, DIM, 1);
}

// round 7
// speedup vs baseline: 1.1499x; 1.1499x over previous
#include <cuda_runtime.h>
#include <cstdint>

#define NHEADS 12
#define HD 64
#define NB 16
#define SEQ 577
#define DIM 768
#define MROWS (NB * SEQ)        // 9232
#define NQKV (3 * DIM)          // 2304
#define NBH (NB * NHEADS)       // 192
#define ATT_SCALE 0.125f
#define EPSF 1e-6f
#define AST 36                  // A smem stride: bank(4g+t), conflict-free
#define BST 72                  // B smem stride: bank(8t+g), conflict-free
#define KST 68                  // attn smem stride

// Scratch (no allocations allowed)
__device__ float g_qkv[(size_t)3 * NBH * SEQ * HD];   // [3,B,H,N,64]
__device__ float g_attn[(size_t)MROWS * DIM];         // [B*N, 768]
__device__ float g_vsum[(size_t)NBH * HD];            // per (b,h): sum_keys V

__device__ __forceinline__ uint32_t f2tf32(float x) {
    uint32_t r;
    asm("cvt.rna.tf32.f32 %0, %1;" : "=r"(r) : "f"(x));
    return r;
}
__device__ __forceinline__ void mma1688(float d[4], const uint32_t a[4], const uint32_t b[2]) {
    asm volatile(
        "mma.sync.aligned.m16n8k8.row.col.f32.tf32.tf32.f32 "
        "{%0,%1,%2,%3}, {%4,%5,%6,%7}, {%8,%9}, {%0,%1,%2,%3};"
        : "+f"(d[0]), "+f"(d[1]), "+f"(d[2]), "+f"(d[3])
        : "r"(a[0]), "r"(a[1]), "r"(a[2]), "r"(a[3]), "r"(b[0]), "r"(b[1]));
}
__device__ __forceinline__ float4 round4(float4 v) {
    float4 w;
    w.x = __uint_as_float(f2tf32(v.x));
    w.y = __uint_as_float(f2tf32(v.y));
    w.z = __uint_as_float(f2tf32(v.z));
    w.w = __uint_as_float(f2tf32(v.w));
    return w;
}

// ---------------------------------------------------------------------------
// tf32 mma GEMM, R3-proven structure + direct [k][n] weight consumption.
// C[m0:+128, n0:+64] = A[.,768] @ W[768, ldB][:, n0:+64] (+bias)
// 8 warps = 4M x 2N, warp tile 32x32, K-tile 32, static smem (4 CTAs/SM).
// mode 0: scatter into g_qkv [3,B,H,N,64]; mode 1: row-major out.
// ---------------------------------------------------------------------------
__global__ __launch_bounds__(256, 2) void gemm_mma(const float* __restrict__ A,
                                                   const float* __restrict__ W,
                                                   const float* __restrict__ bias,
                                                   float* __restrict__ outp,
                                                   int Mtotal, int ldB, int mode) {
    __shared__ float As[128 * AST];   // 128 rows x 32 k
    __shared__ float Bs[32 * BST];    // 32 k-rows x 64 n

    const int tid = threadIdx.x;
    const int lane = tid & 31, wid = tid >> 5;
    const int warpM = wid >> 1, warpN = wid & 1;
    const int g = lane >> 2, t = lane & 3;
    const int m0 = blockIdx.y * 128, n0 = blockIdx.x * 64;

    float d[2][4][4];
#pragma unroll
    for (int i = 0; i < 2; i++)
#pragma unroll
        for (int j = 0; j < 4; j++)
#pragma unroll
            for (int c = 0; c < 4; c++) d[i][j][c] = 0.f;

    for (int kt = 0; kt < 24; kt++) {
        const int k0 = kt * 32;
        // A tile: 128 x 32, 4 float4/thread
#pragma unroll
        for (int u = 0; u < 4; u++) {
            int idx = tid + u * 256;
            int r = idx >> 3, c4 = idx & 7;
            float4 v = make_float4(0.f, 0.f, 0.f, 0.f);
            if (m0 + r < Mtotal) v = *(const float4*)(A + (size_t)(m0 + r) * DIM + k0 + c4 * 4);
            *(float4*)(As + r * AST + c4 * 4) = round4(v);
        }
        // B tile: 32 k-rows x 64 n, 2 float4/thread (coalesced row loads)
#pragma unroll
        for (int u = 0; u < 2; u++) {
            int idx = tid + u * 256;
            int r = idx >> 4, c4 = idx & 15;
            float4 v = *(const float4*)(W + (size_t)(k0 + r) * ldB + n0 + c4 * 4);
            *(float4*)(Bs + r * BST + c4 * 4) = round4(v);
        }
        __syncthreads();

#pragma unroll
        for (int ks = 0; ks < 4; ks++) {
            const int kb = ks * 8;
            uint32_t af[2][4], bf[4][2];
#pragma unroll
            for (int mf = 0; mf < 2; mf++) {
                int r0 = warpM * 32 + mf * 16 + g;
                af[mf][0] = __float_as_uint(As[r0 * AST + kb + t]);
                af[mf][1] = __float_as_uint(As[(r0 + 8) * AST + kb + t]);
                af[mf][2] = __float_as_uint(As[r0 * AST + kb + t + 4]);
                af[mf][3] = __float_as_uint(As[(r0 + 8) * AST + kb + t + 4]);
            }
#pragma unroll
            for (int nf = 0; nf < 4; nf++) {
                int c0 = warpN * 32 + nf * 8 + g;
                bf[nf][0] = __float_as_uint(Bs[(kb + t) * BST + c0]);
                bf[nf][1] = __float_as_uint(Bs[(kb + t + 4) * BST + c0]);
            }
#pragma unroll
            for (int mf = 0; mf < 2; mf++)
#pragma unroll
                for (int nf = 0; nf < 4; nf++) mma1688(d[mf][nf], af[mf], bf[nf]);
        }
        __syncthreads();
    }

#pragma unroll
    for (int mf = 0; mf < 2; mf++) {
#pragma unroll
        for (int half = 0; half < 2; half++) {
            int row = m0 + warpM * 32 + mf * 16 + g + half * 8;
            if (row >= Mtotal) continue;
            int b_ = row / SEQ, n = row - (row / SEQ) * SEQ;
#pragma unroll
            for (int nf = 0; nf < 4; nf++) {
                int col = n0 + warpN * 32 + nf * 8 + 2 * t;
                float2 w;
                w.x = d[mf][nf][half * 2 + 0] + bias[col + 0];
                w.y = d[mf][nf][half * 2 + 1] + bias[col + 1];
                if (mode == 0) {
                    int s = col / DIM;
                    int rem = col - s * DIM;
                    int h = rem >> 6, dd = rem & 63;
                    *(float2*)(g_qkv +
                        (((size_t)s * NBH + b_ * NHEADS + h) * SEQ + n) * HD + dd) = w;
                } else {
                    *(float2*)(outp + (size_t)row * DIM + col) = w;
                }
            }
        }
    }
}

// ---------------------------------------------------------------------------
// Per-(b,h) column sums of V, 256 threads.
// ---------------------------------------------------------------------------
__global__ __launch_bounds__(256) void vsum_kernel() {
    __shared__ float part[4][64];
    const int bh = blockIdx.x;
    const int c = threadIdx.x & 63, gr = threadIdx.x >> 6;
    const float* Vg = g_qkv + (size_t)(2 * NBH + bh) * SEQ * HD;
    float s = 0.f;
    for (int k = gr; k < SEQ; k += 4) s += Vg[(size_t)k * HD + c];
    part[gr][c] = s;
    __syncthreads();
    if (gr == 0)
        g_vsum[bh * HD + c] = part[0][c] + part[1][c] + part[2][c] + part[3][c];
}

// ---------------------------------------------------------------------------
// Tensor-core attention (validated R5 version, unchanged).
// ---------------------------------------------------------------------------
__global__ __launch_bounds__(256, 2) void attn_mma(const float* __restrict__ policy) {
    extern __shared__ float sm[];
    float* Ks = sm;
    float* Vs = sm + 64 * KST;
    float* Ps = sm + 128 * KST;
    float* pol = sm + 256 * KST;

    const int bh = blockIdx.y;
    const int b_ = bh / NHEADS, h = bh % NHEADS;
    const int q0 = blockIdx.x * 128;
    const float* Qg = g_qkv + (size_t)bh * SEQ * HD;
    const float* Kg = g_qkv + (size_t)(NBH + bh) * SEQ * HD;
    const float* Vg = g_qkv + (size_t)(2 * NBH + bh) * SEQ * HD;

    const int tid = threadIdx.x;
    const int lane = tid & 31, w = tid >> 5;
    const int g = lane >> 2, t = lane & 3;
    const int r0 = q0 + w * 16 + g;

    uint32_t aq[8][4];
#pragma unroll
    for (int ks = 0; ks < 8; ks++) {
        int c = ks * 8 + t;
        aq[ks][0] = (r0 < SEQ)     ? f2tf32(Qg[(size_t)r0 * HD + c])           : 0u;
        aq[ks][1] = (r0 + 8 < SEQ) ? f2tf32(Qg[(size_t)(r0 + 8) * HD + c])     : 0u;
        aq[ks][2] = (r0 < SEQ)     ? f2tf32(Qg[(size_t)r0 * HD + c + 4])       : 0u;
        aq[ks][3] = (r0 + 8 < SEQ) ? f2tf32(Qg[(size_t)(r0 + 8) * HD + c + 4]) : 0u;
    }

    float mrow[2] = {-1e30f, -1e30f}, lrow[2] = {0.f, 0.f};
    float o[8][4];
#pragma unroll
    for (int nf = 0; nf < 8; nf++)
#pragma unroll
        for (int c = 0; c < 4; c++) o[nf][c] = 0.f;

    for (int kc = 0; kc < 10; kc++) {
        const int kb = kc * 64;
        __syncthreads();
#pragma unroll
        for (int u = 0; u < 4; u++) {
            int idx = tid + u * 256;
            int r = idx >> 4, c4 = idx & 15;
            float4 v = make_float4(0.f, 0.f, 0.f, 0.f);
            if (kb + r < SEQ) v = *(const float4*)(Kg + (size_t)(kb + r) * HD + c4 * 4);
            *(float4*)(Ks + r * KST + c4 * 4) = round4(v);
        }
#pragma unroll
        for (int u = 0; u < 4; u++) {
            int idx = tid + u * 256;
            int r = idx >> 4, c4 = idx & 15;
            float4 v = make_float4(0.f, 0.f, 0.f, 0.f);
            if (kb + r < SEQ) v = *(const float4*)(Vg + (size_t)(kb + r) * HD + c4 * 4);
            *(float4*)(Vs + r * KST + c4 * 4) = round4(v);
        }
        if (tid < 64) pol[tid] = (kb + tid < SEQ) ? policy[b_ * SEQ + kb + tid] : 0.f;
        __syncthreads();

        float s[8][4];
#pragma unroll
        for (int nf = 0; nf < 8; nf++)
#pragma unroll
            for (int c = 0; c < 4; c++) s[nf][c] = 0.f;
#pragma unroll
        for (int ks = 0; ks < 8; ks++) {
            const int kcol = ks * 8;
#pragma unroll
            for (int nf = 0; nf < 8; nf++) {
                uint32_t bf[2];
                bf[0] = __float_as_uint(Ks[(nf * 8 + g) * KST + kcol + t]);
                bf[1] = __float_as_uint(Ks[(nf * 8 + g) * KST + kcol + t + 4]);
                mma1688(s[nf], aq[ks], bf);
            }
        }

#pragma unroll
        for (int nf = 0; nf < 8; nf++)
#pragma unroll
            for (int c = 0; c < 4; c++) {
                int key = kb + nf * 8 + 2 * t + (c & 1);
                s[nf][c] = (key < SEQ) ? s[nf][c] * ATT_SCALE : -1e30f;
            }

#pragma unroll
        for (int half = 0; half < 2; half++) {
            const int qglob = r0 + 8 * half;
            float rm = -1e30f;
#pragma unroll
            for (int nf = 0; nf < 8; nf++)
                rm = fmaxf(rm, fmaxf(s[nf][half * 2], s[nf][half * 2 + 1]));
            rm = fmaxf(rm, __shfl_xor_sync(0xffffffffu, rm, 1));
            rm = fmaxf(rm, __shfl_xor_sync(0xffffffffu, rm, 2));
            float nm = fmaxf(mrow[half], rm);
            float corr = __expf(mrow[half] - nm);
            mrow[half] = nm;
            float ls = 0.f;
#pragma unroll
            for (int nf = 0; nf < 8; nf++) {
#pragma unroll
                for (int c = 0; c < 2; c++) {
                    int kl = nf * 8 + 2 * t + c;
                    int key = kb + kl;
                    bool keep = (pol[kl] > 0.5f) || (key == qglob);
                    float p = keep ? __expf(s[nf][half * 2 + c] - nm) : 0.f;
                    s[nf][half * 2 + c] = p;
                    ls += p;
                }
            }
            ls += __shfl_xor_sync(0xffffffffu, ls, 1);
            ls += __shfl_xor_sync(0xffffffffu, ls, 2);
            lrow[half] = lrow[half] * corr + ls;
#pragma unroll
            for (int nf = 0; nf < 8; nf++) {
                o[nf][half * 2] *= corr;
                o[nf][half * 2 + 1] *= corr;
            }
        }

#pragma unroll
        for (int nf = 0; nf < 8; nf++) {
#pragma unroll
            for (int half = 0; half < 2; half++) {
                float2 pv;
                pv.x = __uint_as_float(f2tf32(s[nf][half * 2]));
                pv.y = __uint_as_float(f2tf32(s[nf][half * 2 + 1]));
                *(float2*)(Ps + (w * 16 + g + 8 * half) * KST + nf * 8 + 2 * t) = pv;
            }
        }

#pragma unroll
        for (int ks = 0; ks < 8; ks++) {
            uint32_t ap[4];
            const int kcol = ks * 8;
            ap[0] = __float_as_uint(Ps[(w * 16 + g) * KST + kcol + t]);
            ap[1] = __float_as_uint(Ps[(w * 16 + g + 8) * KST + kcol + t]);
            ap[2] = __float_as_uint(Ps[(w * 16 + g) * KST + kcol + t + 4]);
            ap[3] = __float_as_uint(Ps[(w * 16 + g + 8) * KST + kcol + t + 4]);
#pragma unroll
            for (int nf = 0; nf < 8; nf++) {
                uint32_t bf[2];
                bf[0] = __float_as_uint(Vs[(kcol + t) * KST + nf * 8 + g]);
                bf[1] = __float_as_uint(Vs[(kcol + t + 4) * KST + nf * 8 + g]);
                mma1688(o[nf], ap, bf);
            }
        }
    }

    const float epsn = EPSF / (float)SEQ;
#pragma unroll
    for (int half = 0; half < 2; half++) {
        int qglob = r0 + 8 * half;
        if (qglob >= SEQ) continue;
        float inv = 1.f / (lrow[half] + EPSF);
#pragma unroll
        for (int nf = 0; nf < 8; nf++) {
            int dd = nf * 8 + 2 * t;
            float2 vs = *(const float2*)(g_vsum + bh * HD + dd);
            float2 ww;
            ww.x = (o[nf][half * 2] + epsn * vs.x) * inv;
            ww.y = (o[nf][half * 2 + 1] + epsn * vs.y) * inv;
            *(float2*)(g_attn + ((size_t)b_ * SEQ + qglob) * DIM + h * HD + dd) = ww;
        }
    }
}

// ---------------------------------------------------------------------------
extern "C" void kernel_launch(void* const* d_in, const int* in_sizes, int n_in,
                              void* d_out, int out_size) {
    const float* x      = (const float*)d_in[0];
    const float* policy = (const float*)d_in[1];
    const float* Wqkv   = (const float*)d_in[2];
    const float* bqkv   = (const float*)d_in[3];
    const float* Wproj  = (const float*)d_in[4];
    const float* bproj  = (const float*)d_in[5];
    float* out = (float*)d_out;
    (void)in_sizes; (void)n_in; (void)out_size;

    void* p_attn = nullptr;
    cudaGetSymbolAddress(&p_attn, g_attn);

    // 1) QKV projection (tensor cores, direct [k][n] weights), scatter
    dim3 g1(NQKV / 64, (MROWS + 127) / 128);
    gemm_mma<<<g1, 256>>>(x, Wqkv, bqkv, nullptr, MROWS, NQKV, 0);

    // 1b) per-(b,h) V column sums
    vsum_kernel<<<NBH, 256>>>();

    // 2) tensor-core policy-masked flash attention
    const int asmem = (256 * KST + 64) * 4;
    cudaFuncSetAttribute(attn_mma, cudaFuncAttributeMaxDynamicSharedMemorySize, asmem);
    dim3 g2((SEQ + 127) / 128, NBH);
    attn_mma<<<g2, 256, asmem>>>(policy);

    // 3) output projection (tensor cores)
    dim3 g3(DIM / 64, (MROWS + 127) / 128);
    gemm_mma<<<g3, 256>>>((const float*)p_attn, Wproj, bproj, out, MROWS, DIM, 1);
}

// round 8
// speedup vs baseline: 1.3096x; 1.1388x over previous
#include <cuda_runtime.h>
#include <cstdint>

#define NHEADS 12
#define HD 64
#define NB 16
#define SEQ 577
#define DIM 768
#define MROWS (NB * SEQ)        // 9232
#define NQKV (3 * DIM)          // 2304
#define NBH (NB * NHEADS)       // 192
#define ATT_SCALE 0.125f
#define EPSF 1e-6f
#define AST 36                  // A smem stride: bank(4g+t), conflict-free
#define BST2 136                // B smem stride (128-wide N): bank(8t+g), conflict-free
#define KST 68                  // attn smem stride
#define GBUF (128 * AST + 32 * BST2)   // floats per gemm pipeline stage (8960)

// Scratch (no allocations allowed)
__device__ float g_qkv[(size_t)3 * NBH * SEQ * HD];   // [3,B,H,N,64] (tf32-rounded)
__device__ float g_attn[(size_t)MROWS * DIM];         // [B*N, 768]   (tf32-rounded)
__device__ float g_vsum[(size_t)NBH * HD];
__device__ float g_xr[(size_t)MROWS * DIM];           // tf32-rounded x
__device__ float g_wq[(size_t)DIM * NQKV];            // tf32-rounded Wqkv
__device__ float g_wp[(size_t)DIM * DIM];             // tf32-rounded Wproj

__device__ __forceinline__ uint32_t f2tf32(float x) {
    uint32_t r;
    asm("cvt.rna.tf32.f32 %0, %1;" : "=r"(r) : "f"(x));
    return r;
}
__device__ __forceinline__ void mma1688(float d[4], const uint32_t a[4], const uint32_t b[2]) {
    asm volatile(
        "mma.sync.aligned.m16n8k8.row.col.f32.tf32.tf32.f32 "
        "{%0,%1,%2,%3}, {%4,%5,%6,%7}, {%8,%9}, {%0,%1,%2,%3};"
        : "+f"(d[0]), "+f"(d[1]), "+f"(d[2]), "+f"(d[3])
        : "r"(a[0]), "r"(a[1]), "r"(a[2]), "r"(a[3]), "r"(b[0]), "r"(b[1]));
}
__device__ __forceinline__ float4 round4(float4 v) {
    float4 w;
    w.x = __uint_as_float(f2tf32(v.x));
    w.y = __uint_as_float(f2tf32(v.y));
    w.z = __uint_as_float(f2tf32(v.z));
    w.w = __uint_as_float(f2tf32(v.w));
    return w;
}
__device__ __forceinline__ uint32_t smem_u32(const void* p) {
    uint32_t a;
    asm("{ .reg .u64 t; cvta.to.shared.u64 t, %1; cvt.u32.u64 %0, t; }" : "=r"(a) : "l"(p));
    return a;
}
__device__ __forceinline__ void cpasync16(uint32_t dst, const void* src, int szbytes) {
    asm volatile("cp.async.ca.shared.global [%0], [%1], 16, %2;"
                 :: "r"(dst), "l"(src), "r"(szbytes));
}

// ---------------------------------------------------------------------------
// Elementwise tf32 pre-round (float4 grid-stride)
// ---------------------------------------------------------------------------
__global__ __launch_bounds__(256) void round_buf(const float4* __restrict__ in,
                                                 float4* __restrict__ out, int n4) {
    int i = blockIdx.x * blockDim.x + threadIdx.x;
    int stride = gridDim.x * blockDim.x;
    for (; i < n4; i += stride) out[i] = round4(in[i]);
}

// ---------------------------------------------------------------------------
// tf32 mma GEMM, cp.async double-buffered, CTA tile 128x128.
// C[m0:+128, n0:+128] = A[.,768] @ W[768, ldB][:, n0:+128] (+bias)
// 8 warps = 4M x 2N, warp tile 32x64 (2mf x 8nf). Inputs pre-rounded.
// mode 0: scatter into g_qkv (rounded); mode 1: row-major out (final).
// ---------------------------------------------------------------------------
__global__ __launch_bounds__(256, 2) void gemm_mma(const float* __restrict__ A,
                                                   const float* __restrict__ W,
                                                   const float* __restrict__ bias,
                                                   float* __restrict__ outp,
                                                   int Mtotal, int ldB, int mode) {
    extern __shared__ float smg[];
    const uint32_t sbase = smem_u32(smg);

    const int tid = threadIdx.x;
    const int lane = tid & 31, wid = tid >> 5;
    const int warpM = wid >> 1, warpN = wid & 1;
    const int g = lane >> 2, t = lane & 3;
    const int m0 = blockIdx.y * 128, n0 = blockIdx.x * 128;

    // stage tile kt into buffer b (cp.async, no registers, no cvt)
#define STAGE(kt, b)                                                              \
    {                                                                             \
        const int k0 = (kt) * 32;                                                 \
        const uint32_t base = sbase + (uint32_t)(b) * (GBUF * 4);                 \
        _Pragma("unroll")                                                         \
        for (int u = 0; u < 4; u++) {                                             \
            int idx = tid + u * 256;                                              \
            int r = idx >> 3, c4 = idx & 7;                                       \
            int row = m0 + r;                                                     \
            int rc = row < Mtotal ? row : Mtotal - 1;                             \
            cpasync16(base + (uint32_t)(r * AST + c4 * 4) * 4,                    \
                      A + (size_t)rc * DIM + k0 + c4 * 4,                         \
                      row < Mtotal ? 16 : 0);                                     \
        }                                                                         \
        _Pragma("unroll")                                                         \
        for (int u = 0; u < 4; u++) {                                             \
            int idx = tid + u * 256;                                              \
            int r = idx >> 5, c4 = idx & 31;                                      \
            cpasync16(base + (uint32_t)(128 * AST + r * BST2 + c4 * 4) * 4,       \
                      W + (size_t)(k0 + r) * ldB + n0 + c4 * 4, 16);              \
        }                                                                         \
    }

    float d[2][8][4];
#pragma unroll
    for (int i = 0; i < 2; i++)
#pragma unroll
        for (int j = 0; j < 8; j++)
#pragma unroll
            for (int c = 0; c < 4; c++) d[i][j][c] = 0.f;

    STAGE(0, 0);
    asm volatile("cp.async.commit_group;");
    asm volatile("cp.async.wait_group 0;");
    __syncthreads();

    for (int kt = 0; kt < 24; kt++) {
        const int cur = kt & 1;
        if (kt < 23) {
            STAGE(kt + 1, 1 - cur);
            asm volatile("cp.async.commit_group;");
        }

        const float* Ab = smg + cur * GBUF;
        const float* Bb = Ab + 128 * AST;
#pragma unroll
        for (int ks = 0; ks < 4; ks++) {
            const int kb = ks * 8;
            uint32_t af[2][4], bf[8][2];
#pragma unroll
            for (int mf = 0; mf < 2; mf++) {
                int r0 = warpM * 32 + mf * 16 + g;
                af[mf][0] = __float_as_uint(Ab[r0 * AST + kb + t]);
                af[mf][1] = __float_as_uint(Ab[(r0 + 8) * AST + kb + t]);
                af[mf][2] = __float_as_uint(Ab[r0 * AST + kb + t + 4]);
                af[mf][3] = __float_as_uint(Ab[(r0 + 8) * AST + kb + t + 4]);
            }
#pragma unroll
            for (int nf = 0; nf < 8; nf++) {
                int c0 = warpN * 64 + nf * 8 + g;
                bf[nf][0] = __float_as_uint(Bb[(kb + t) * BST2 + c0]);
                bf[nf][1] = __float_as_uint(Bb[(kb + t + 4) * BST2 + c0]);
            }
#pragma unroll
            for (int mf = 0; mf < 2; mf++)
#pragma unroll
                for (int nf = 0; nf < 8; nf++) mma1688(d[mf][nf], af[mf], bf[nf]);
        }
        if (kt < 23) asm volatile("cp.async.wait_group 0;");
        __syncthreads();
    }

#pragma unroll
    for (int mf = 0; mf < 2; mf++) {
#pragma unroll
        for (int half = 0; half < 2; half++) {
            int row = m0 + warpM * 32 + mf * 16 + g + half * 8;
            if (row >= Mtotal) continue;
            int b_ = row / SEQ, n = row - (row / SEQ) * SEQ;
#pragma unroll
            for (int nf = 0; nf < 8; nf++) {
                int col = n0 + warpN * 64 + nf * 8 + 2 * t;
                float2 w;
                w.x = d[mf][nf][half * 2 + 0] + bias[col + 0];
                w.y = d[mf][nf][half * 2 + 1] + bias[col + 1];
                if (mode == 0) {
                    // store tf32-rounded so attention consumes pre-rounded data
                    w.x = __uint_as_float(f2tf32(w.x));
                    w.y = __uint_as_float(f2tf32(w.y));
                    int s = col / DIM;
                    int rem = col - s * DIM;
                    int h = rem >> 6, dd = rem & 63;
                    *(float2*)(g_qkv +
                        (((size_t)s * NBH + b_ * NHEADS + h) * SEQ + n) * HD + dd) = w;
                } else {
                    *(float2*)(outp + (size_t)row * DIM + col) = w;
                }
            }
        }
    }
#undef STAGE
}

// ---------------------------------------------------------------------------
// Per-(b,h) column sums of V.
// ---------------------------------------------------------------------------
__global__ __launch_bounds__(256) void vsum_kernel() {
    __shared__ float part[4][64];
    const int bh = blockIdx.x;
    const int c = threadIdx.x & 63, gr = threadIdx.x >> 6;
    const float* Vg = g_qkv + (size_t)(2 * NBH + bh) * SEQ * HD;
    float s = 0.f;
    for (int k = gr; k < SEQ; k += 4) s += Vg[(size_t)k * HD + c];
    part[gr][c] = s;
    __syncthreads();
    if (gr == 0)
        g_vsum[bh * HD + c] = part[0][c] + part[1][c] + part[2][c] + part[3][c];
}

// ---------------------------------------------------------------------------
// Tensor-core attention (validated R5 version; only g_attn store now rounded).
// ---------------------------------------------------------------------------
__global__ __launch_bounds__(256, 2) void attn_mma(const float* __restrict__ policy) {
    extern __shared__ float sm[];
    float* Ks = sm;
    float* Vs = sm + 64 * KST;
    float* Ps = sm + 128 * KST;
    float* pol = sm + 256 * KST;

    const int bh = blockIdx.y;
    const int b_ = bh / NHEADS, h = bh % NHEADS;
    const int q0 = blockIdx.x * 128;
    const float* Qg = g_qkv + (size_t)bh * SEQ * HD;
    const float* Kg = g_qkv + (size_t)(NBH + bh) * SEQ * HD;
    const float* Vg = g_qkv + (size_t)(2 * NBH + bh) * SEQ * HD;

    const int tid = threadIdx.x;
    const int lane = tid & 31, w = tid >> 5;
    const int g = lane >> 2, t = lane & 3;
    const int r0 = q0 + w * 16 + g;

    uint32_t aq[8][4];
#pragma unroll
    for (int ks = 0; ks < 8; ks++) {
        int c = ks * 8 + t;
        aq[ks][0] = (r0 < SEQ)     ? f2tf32(Qg[(size_t)r0 * HD + c])           : 0u;
        aq[ks][1] = (r0 + 8 < SEQ) ? f2tf32(Qg[(size_t)(r0 + 8) * HD + c])     : 0u;
        aq[ks][2] = (r0 < SEQ)     ? f2tf32(Qg[(size_t)r0 * HD + c + 4])       : 0u;
        aq[ks][3] = (r0 + 8 < SEQ) ? f2tf32(Qg[(size_t)(r0 + 8) * HD + c + 4]) : 0u;
    }

    float mrow[2] = {-1e30f, -1e30f}, lrow[2] = {0.f, 0.f};
    float o[8][4];
#pragma unroll
    for (int nf = 0; nf < 8; nf++)
#pragma unroll
        for (int c = 0; c < 4; c++) o[nf][c] = 0.f;

    for (int kc = 0; kc < 10; kc++) {
        const int kb = kc * 64;
        __syncthreads();
#pragma unroll
        for (int u = 0; u < 4; u++) {
            int idx = tid + u * 256;
            int r = idx >> 4, c4 = idx & 15;
            float4 v = make_float4(0.f, 0.f, 0.f, 0.f);
            if (kb + r < SEQ) v = *(const float4*)(Kg + (size_t)(kb + r) * HD + c4 * 4);
            *(float4*)(Ks + r * KST + c4 * 4) = v;
        }
#pragma unroll
        for (int u = 0; u < 4; u++) {
            int idx = tid + u * 256;
            int r = idx >> 4, c4 = idx & 15;
            float4 v = make_float4(0.f, 0.f, 0.f, 0.f);
            if (kb + r < SEQ) v = *(const float4*)(Vg + (size_t)(kb + r) * HD + c4 * 4);
            *(float4*)(Vs + r * KST + c4 * 4) = v;
        }
        if (tid < 64) pol[tid] = (kb + tid < SEQ) ? policy[b_ * SEQ + kb + tid] : 0.f;
        __syncthreads();

        float s[8][4];
#pragma unroll
        for (int nf = 0; nf < 8; nf++)
#pragma unroll
            for (int c = 0; c < 4; c++) s[nf][c] = 0.f;
#pragma unroll
        for (int ks = 0; ks < 8; ks++) {
            const int kcol = ks * 8;
#pragma unroll
            for (int nf = 0; nf < 8; nf++) {
                uint32_t bf[2];
                bf[0] = __float_as_uint(Ks[(nf * 8 + g) * KST + kcol + t]);
                bf[1] = __float_as_uint(Ks[(nf * 8 + g) * KST + kcol + t + 4]);
                mma1688(s[nf], aq[ks], bf);
            }
        }

#pragma unroll
        for (int nf = 0; nf < 8; nf++)
#pragma unroll
            for (int c = 0; c < 4; c++) {
                int key = kb + nf * 8 + 2 * t + (c & 1);
                s[nf][c] = (key < SEQ) ? s[nf][c] * ATT_SCALE : -1e30f;
            }

#pragma unroll
        for (int half = 0; half < 2; half++) {
            const int qglob = r0 + 8 * half;
            float rm = -1e30f;
#pragma unroll
            for (int nf = 0; nf < 8; nf++)
                rm = fmaxf(rm, fmaxf(s[nf][half * 2], s[nf][half * 2 + 1]));
            rm = fmaxf(rm, __shfl_xor_sync(0xffffffffu, rm, 1));
            rm = fmaxf(rm, __shfl_xor_sync(0xffffffffu, rm, 2));
            float nm = fmaxf(mrow[half], rm);
            float corr = __expf(mrow[half] - nm);
            mrow[half] = nm;
            float ls = 0.f;
#pragma unroll
            for (int nf = 0; nf < 8; nf++) {
#pragma unroll
                for (int c = 0; c < 2; c++) {
                    int kl = nf * 8 + 2 * t + c;
                    int key = kb + kl;
                    bool keep = (pol[kl] > 0.5f) || (key == qglob);
                    float p = keep ? __expf(s[nf][half * 2 + c] - nm) : 0.f;
                    s[nf][half * 2 + c] = p;
                    ls += p;
                }
            }
            ls += __shfl_xor_sync(0xffffffffu, ls, 1);
            ls += __shfl_xor_sync(0xffffffffu, ls, 2);
            lrow[half] = lrow[half] * corr + ls;
#pragma unroll
            for (int nf = 0; nf < 8; nf++) {
                o[nf][half * 2] *= corr;
                o[nf][half * 2 + 1] *= corr;
            }
        }

#pragma unroll
        for (int nf = 0; nf < 8; nf++) {
#pragma unroll
            for (int half = 0; half < 2; half++) {
                float2 pv;
                pv.x = __uint_as_float(f2tf32(s[nf][half * 2]));
                pv.y = __uint_as_float(f2tf32(s[nf][half * 2 + 1]));
                *(float2*)(Ps + (w * 16 + g + 8 * half) * KST + nf * 8 + 2 * t) = pv;
            }
        }

#pragma unroll
        for (int ks = 0; ks < 8; ks++) {
            uint32_t ap[4];
            const int kcol = ks * 8;
            ap[0] = __float_as_uint(Ps[(w * 16 + g) * KST + kcol + t]);
            ap[1] = __float_as_uint(Ps[(w * 16 + g + 8) * KST + kcol + t]);
            ap[2] = __float_as_uint(Ps[(w * 16 + g) * KST + kcol + t + 4]);
            ap[3] = __float_as_uint(Ps[(w * 16 + g + 8) * KST + kcol + t + 4]);
#pragma unroll
            for (int nf = 0; nf < 8; nf++) {
                uint32_t bf[2];
                bf[0] = __float_as_uint(Vs[(kcol + t) * KST + nf * 8 + g]);
                bf[1] = __float_as_uint(Vs[(kcol + t + 4) * KST + nf * 8 + g]);
                mma1688(o[nf], ap, bf);
            }
        }
    }

    const float epsn = EPSF / (float)SEQ;
#pragma unroll
    for (int half = 0; half < 2; half++) {
        int qglob = r0 + 8 * half;
        if (qglob >= SEQ) continue;
        float inv = 1.f / (lrow[half] + EPSF);
#pragma unroll
        for (int nf = 0; nf < 8; nf++) {
            int dd = nf * 8 + 2 * t;
            float2 vs = *(const float2*)(g_vsum + bh * HD + dd);
            float2 ww;
            ww.x = __uint_as_float(f2tf32((o[nf][half * 2] + epsn * vs.x) * inv));
            ww.y = __uint_as_float(f2tf32((o[nf][half * 2 + 1] + epsn * vs.y) * inv));
            *(float2*)(g_attn + ((size_t)b_ * SEQ + qglob) * DIM + h * HD + dd) = ww;
        }
    }
}

// ---------------------------------------------------------------------------
extern "C" void kernel_launch(void* const* d_in, const int* in_sizes, int n_in,
                              void* d_out, int out_size) {
    const float* x      = (const float*)d_in[0];
    const float* policy = (const float*)d_in[1];
    const float* Wqkv   = (const float*)d_in[2];
    const float* bqkv   = (const float*)d_in[3];
    const float* Wproj  = (const float*)d_in[4];
    const float* bproj  = (const float*)d_in[5];
    float* out = (float*)d_out;
    (void)in_sizes; (void)n_in; (void)out_size;

    void *p_attn = nullptr, *p_xr = nullptr, *p_wq = nullptr, *p_wp = nullptr;
    cudaGetSymbolAddress(&p_attn, g_attn);
    cudaGetSymbolAddress(&p_xr, g_xr);
    cudaGetSymbolAddress(&p_wq, g_wq);
    cudaGetSymbolAddress(&p_wp, g_wp);

    // 0) pre-round inputs to tf32
    round_buf<<<1184, 256>>>((const float4*)x, (float4*)p_xr, MROWS * DIM / 4);
    round_buf<<<592, 256>>>((const float4*)Wqkv, (float4*)p_wq, DIM * NQKV / 4);
    round_buf<<<296, 256>>>((const float4*)Wproj, (float4*)p_wp, DIM * DIM / 4);

    const int gsmem = 2 * GBUF * 4;   // 71680 B
    cudaFuncSetAttribute(gemm_mma, cudaFuncAttributeMaxDynamicSharedMemorySize, gsmem);

    // 1) QKV projection, scatter (rounded) to [3,B,H,N,64]
    dim3 g1(NQKV / 128, (MROWS + 127) / 128);
    gemm_mma<<<g1, 256, gsmem>>>((const float*)p_xr, (const float*)p_wq, bqkv,
                                 nullptr, MROWS, NQKV, 0);

    // 1b) per-(b,h) V column sums
    vsum_kernel<<<NBH, 256>>>();

    // 2) tensor-core policy-masked flash attention
    const int asmem = (256 * KST + 64) * 4;
    cudaFuncSetAttribute(attn_mma, cudaFuncAttributeMaxDynamicSharedMemorySize, asmem);
    dim3 g2((SEQ + 127) / 128, NBH);
    attn_mma<<<g2, 256, asmem>>>(policy);

    // 3) output projection
    dim3 g3(DIM / 128, (MROWS + 127) / 128);
    gemm_mma<<<g3, 256, gsmem>>>((const float*)p_attn, (const float*)p_wp, bproj,
                                 out, MROWS, DIM, 1);
}